// round 1
// baseline (speedup 1.0000x reference)
#include <cuda_runtime.h>
#include <math.h>

// Problem constants
#define BV 512
#define TV 64
#define FV 256
#define HV 1024

// Output layout: x_imp [B,T,F] | reconstruction [B,T,F] | h_fin [B,H] | x_loss | kl_loss
#define OFF_REC   (BV*TV*FV)            // 8388608
#define OFF_HFIN  (2*BV*TV*FV)          // 16777216
#define OFF_LOSS  (2*BV*TV*FV + BV*HV)  // 17301504

#define NB2 32   // number of blocks in GEMM2 grid (loss partials per step)

// ---------------- scratch (__device__ globals; no allocation allowed) ----------------
__device__ float g_h[BV*HV];                      // hidden state (in-place updated)
__device__ float g_xh[BV*FV];                     // x_h per step
__device__ float g_gh[BV*3*HV];                   // h @ Whh^T + bhh per step
__device__ float g_gi[BV*3*HV];                   // rnn_in @ Wih^T + bih per step
__device__ float g_gammaH[(size_t)TV*BV*HV];      // precomputed exp(-relu(...)) [T][B][H]
__device__ float g_beta[(size_t)TV*BV*FV];        // precomputed beta [T][B][F]
__device__ float g_msum[TV];                      // sum(mask) per step
__device__ float g_lossPart[TV*NB2];              // deterministic loss partials

// ---------------- generic tiled SGEMM: C[m,n] = sum_k A(m,k)*B(n,k), epilogue fused ----
template<int BM,int BN,int BK,int TM,int TN,class AL,class BL,class EP>
__global__ __launch_bounds__(256)
void gemm_k(int K, AL al, BL bl, EP ep) {
    constexpr int TH = (BM/TM)*(BN/TN);   // must be 256
    static_assert(TH == 256, "thread count");
    __shared__ float As[BK][BM+4];
    __shared__ float Bs[BK][BN+4];

    const int tid = threadIdx.x;
    const int bm = blockIdx.y * BM;
    const int bn = blockIdx.x * BN;
    const int tx = tid % (BN/TN);
    const int ty = tid / (BN/TN);

    float acc[TM][TN];
    #pragma unroll
    for (int i = 0; i < TM; i++)
        #pragma unroll
        for (int j = 0; j < TN; j++) acc[i][j] = 0.f;

    for (int k0 = 0; k0 < K; k0 += BK) {
        // load A tile (BM x BK), k fastest for coalescing over contiguous-K sources
        #pragma unroll
        for (int e = tid; e < BM*BK; e += TH) {
            int k = e % BK, m = e / BK;
            As[k][m] = al(bm + m, k0 + k);
        }
        #pragma unroll
        for (int e = tid; e < BN*BK; e += TH) {
            int k = e % BK, n = e / BK;
            Bs[k][n] = bl(bn + n, k0 + k);
        }
        __syncthreads();

        #pragma unroll
        for (int kk = 0; kk < BK; kk++) {
            float a[TM], b[TN];
            #pragma unroll
            for (int i = 0; i < TM; i += 4) {
                float4 v = *(const float4*)&As[kk][ty*TM + i];
                a[i] = v.x; a[i+1] = v.y; a[i+2] = v.z; a[i+3] = v.w;
            }
            #pragma unroll
            for (int j = 0; j < TN; j += 4) {
                float4 v = *(const float4*)&Bs[kk][tx*TN + j];
                b[j] = v.x; b[j+1] = v.y; b[j+2] = v.z; b[j+3] = v.w;
            }
            #pragma unroll
            for (int i = 0; i < TM; i++)
                #pragma unroll
                for (int j = 0; j < TN; j++)
                    acc[i][j] = fmaf(a[i], b[j], acc[i][j]);
        }
        __syncthreads();
    }

    float rsum = 0.f;
    #pragma unroll
    for (int i = 0; i < TM; i++) {
        int gm = bm + ty*TM + i;
        #pragma unroll
        for (int j = 0; j < TN; j++) {
            int gn = bn + tx*TN + j;
            rsum += ep(gm, gn, acc[i][j]);
        }
    }

    if constexpr (EP::RED) {
        __shared__ float red[256];
        red[tid] = rsum;
        __syncthreads();
        for (int s = 128; s > 0; s >>= 1) {
            if (tid < s) red[tid] += red[tid + s];
            __syncthreads();
        }
        if (tid == 0) {
            int lin = blockIdx.y * gridDim.x + blockIdx.x;
            ep.store_partial(lin, red[0]);
        }
    }
}

// ---------------- functors ----------------

// P1: gammaH = exp(-relu(deltas @ Wdh^T + bdh)); M = T*B (m = t*B + b)
struct AL_P1 {
    const float* deltas;
    __device__ float operator()(int m, int k) const {
        int t = m >> 9, b = m & 511;
        return deltas[(b*TV + t)*FV + k];
    }
};
struct BL_P1 {
    const float* Wdh;
    __device__ float operator()(int n, int k) const { return Wdh[n*FV + k]; }
};
struct EP_P1 {
    const float* bdh;
    static constexpr bool RED = false;
    __device__ float operator()(int m, int n, float v) const {
        g_gammaH[(size_t)m*HV + n] = expf(-fmaxf(v + bdh[n], 0.f));
        return 0.f;
    }
    __device__ void store_partial(int, float) const {}
};

// P2: beta = [gamma_x, m] @ Wwc^T + bwc; gamma_x computed on the fly (diag decay)
struct AL_P2 {
    const float* deltas; const float* mask; const float* Wdx; const float* bdx;
    __device__ float operator()(int m, int k) const {
        int t = m >> 9, b = m & 511;
        if (k < FV) {
            float d = deltas[(b*TV + t)*FV + k];
            return expf(-fmaxf(d * Wdx[k*FV + k] + bdx[k], 0.f));
        }
        return mask[(b*TV + t)*FV + (k - FV)];
    }
};
struct BL_P2 {
    const float* Wwc;
    __device__ float operator()(int n, int k) const { return Wwc[n*(2*FV) + k]; }
};
struct EP_P2 {
    const float* bwc;
    static constexpr bool RED = false;
    __device__ float operator()(int m, int n, float v) const {
        g_beta[(size_t)m*FV + n] = v + bwc[n];
        return 0.f;
    }
    __device__ void store_partial(int, float) const {}
};

// G1: [x_h | gh] = (h * gammaH[t]) @ [Wh ; Whh]^T  (N = 256 + 3072 = 3328, K = 1024)
struct AL_G1 {
    int t;
    __device__ float operator()(int m, int k) const {
        int idx = m*HV + k;
        return g_h[idx] * g_gammaH[(size_t)t*BV*HV + idx];
    }
};
struct BL_G1 {
    const float* Wh; const float* Whh;
    __device__ float operator()(int n, int k) const {
        return (n < FV) ? Wh[n*HV + k] : Whh[(n - FV)*HV + k];
    }
};
struct EP_G1 {
    const float* bh; const float* bhh;
    static constexpr bool RED = false;
    __device__ float operator()(int m, int n, float v) const {
        if (n < FV) g_xh[m*FV + n] = v + bh[n];
        else        g_gh[m*3*HV + (n - FV)] = v + bhh[n - FV];
        return 0.f;
    }
    __device__ void store_partial(int, float) const {}
};

// G2: xu = x_r @ Wfr_off^T + bfr ; epilogue computes x_comb, x_imp, loss partials
struct AL_G2 {
    const float* x; const float* mask; int t;
    __device__ float operator()(int m, int k) const {
        int idx = (m*TV + t)*FV + k;
        float mt = mask[idx];
        return mt * x[idx] + (1.f - mt) * g_xh[m*FV + k];
    }
};
struct BL_G2 {
    const float* Wfr;
    __device__ float operator()(int n, int k) const {
        return (n == k) ? 0.f : Wfr[n*FV + k];
    }
};
struct EP_G2 {
    const float* bfr; const float* x; const float* mask;
    float* rec; float* ximp; int t;
    static constexpr bool RED = true;
    __device__ float operator()(int m, int n, float v) const {
        float xu = v + bfr[n];
        float xh = g_xh[m*FV + n];
        float be = g_beta[(size_t)t*BV*FV + m*FV + n];
        float xc = be * xu + (1.f - be) * xh;
        int idx = (m*TV + t)*FV + n;
        float mt = mask[idx], xt = x[idx];
        rec[idx]  = xc;
        ximp[idx] = mt * xt + (1.f - mt) * xc;
        return fabsf(xc - xt) * mt;
    }
    __device__ void store_partial(int lin, float v) const {
        g_lossPart[t*NB2 + lin] = v;
    }
};

// G3: gi = [x_imp, m] @ Wih^T + bih  (K = 512)
struct AL_G3 {
    const float* ximp; const float* mask; int t;
    __device__ float operator()(int m, int k) const {
        if (k < FV) return ximp[(m*TV + t)*FV + k];
        return mask[(m*TV + t)*FV + (k - FV)];
    }
};
struct BL_G3 {
    const float* Wih;
    __device__ float operator()(int n, int k) const { return Wih[n*(2*FV) + k]; }
};
struct EP_G3 {
    const float* bih;
    static constexpr bool RED = false;
    __device__ float operator()(int m, int n, float v) const {
        g_gi[m*3*HV + n] = v + bih[n];
        return 0.f;
    }
    __device__ void store_partial(int, float) const {}
};

// ---------------- elementwise kernels ----------------

__global__ void hinit_k(const float* __restrict__ h0) {
    int idx = blockIdx.x * blockDim.x + threadIdx.x;
    if (idx < BV*HV) g_h[idx] = h0[idx];
}

__global__ void msum_k(const float* __restrict__ mask) {
    int t = blockIdx.x;
    float s = 0.f;
    for (int i = threadIdx.x; i < BV*FV; i += 256) {
        int b = i >> 8, f = i & 255;
        s += mask[(b*TV + t)*FV + f];
    }
    __shared__ float red[256];
    red[threadIdx.x] = s;
    __syncthreads();
    for (int st = 128; st > 0; st >>= 1) {
        if (threadIdx.x < st) red[threadIdx.x] += red[threadIdx.x + st];
        __syncthreads();
    }
    if (threadIdx.x == 0) g_msum[t] = red[0];
}

__global__ void gru_k(int t, float* __restrict__ hfin) {
    int idx = blockIdx.x * blockDim.x + threadIdx.x;  // B*H
    int b = idx >> 10, j = idx & 1023;
    float hd = g_h[idx] * g_gammaH[(size_t)t*BV*HV + idx];
    int base = b*3*HV + j;
    float r = 1.f / (1.f + expf(-(g_gi[base]        + g_gh[base])));
    float z = 1.f / (1.f + expf(-(g_gi[base + HV]   + g_gh[base + HV])));
    float n = tanhf(g_gi[base + 2*HV] + r * g_gh[base + 2*HV]);
    float hn = (1.f - z) * n + z * hd;
    g_h[idx] = hn;
    if (hfin) hfin[idx] = hn;
}

__global__ void final_k(float* __restrict__ out) {
    __shared__ float s[TV];
    int t = threadIdx.x;  // 64 threads
    float acc = 0.f;
    for (int i = 0; i < NB2; i++) acc += g_lossPart[t*NB2 + i];
    s[t] = acc / (g_msum[t] + 1e-12f);
    __syncthreads();
    if (t == 0) {
        float L = 0.f;
        for (int i = 0; i < TV; i++) L += s[i];
        out[OFF_LOSS]     = L;
        out[OFF_LOSS + 1] = 0.f;  // kl_loss
    }
}

// ---------------- launch ----------------

extern "C" void kernel_launch(void* const* d_in, const int* in_sizes, int n_in,
                              void* d_out, int out_size) {
    const float* x      = (const float*)d_in[0];
    const float* mask   = (const float*)d_in[1];
    const float* deltas = (const float*)d_in[2];
    const float* h0     = (const float*)d_in[3];
    const float* Wdh    = (const float*)d_in[4];
    const float* bdh    = (const float*)d_in[5];
    const float* Wdx    = (const float*)d_in[6];
    const float* bdx    = (const float*)d_in[7];
    const float* Wh     = (const float*)d_in[8];
    const float* bh     = (const float*)d_in[9];
    const float* Wfr    = (const float*)d_in[10];
    const float* bfr    = (const float*)d_in[11];
    const float* Wwc    = (const float*)d_in[12];
    const float* bwc    = (const float*)d_in[13];
    const float* Wih    = (const float*)d_in[14];
    const float* bih    = (const float*)d_in[15];
    const float* Whh    = (const float*)d_in[16];
    const float* bhh    = (const float*)d_in[17];

    float* out      = (float*)d_out;
    float* ximp_out = out;
    float* rec_out  = out + OFF_REC;
    float* hfin     = out + OFF_HFIN;

    hinit_k<<<(BV*HV)/256, 256>>>(h0);
    msum_k<<<TV, 256>>>(mask);

    // Precompute gammaH: M=32768, N=1024, K=256
    gemm_k<128,128,8,8,8><<<dim3(1024/128, 32768/128), 256>>>(
        FV, AL_P1{deltas}, BL_P1{Wdh}, EP_P1{bdh});

    // Precompute beta: M=32768, N=256, K=512
    gemm_k<128,128,8,8,8><<<dim3(256/128, 32768/128), 256>>>(
        2*FV, AL_P2{deltas, mask, Wdx, bdx}, BL_P2{Wwc}, EP_P2{bwc});

    for (int t = 0; t < TV; t++) {
        // G1: [x_h | gh], M=512, N=3328, K=1024
        gemm_k<128,128,8,8,8><<<dim3(3328/128, 512/128), 256>>>(
            HV, AL_G1{t}, BL_G1{Wh, Whh}, EP_G1{bh, bhh});

        // G2: xu + fused combine/imputation/loss, M=512, N=256, K=256 (grid = NB2 blocks)
        gemm_k<64,64,16,4,4><<<dim3(256/64, 512/64), 256>>>(
            FV, AL_G2{x, mask, t}, BL_G2{Wfr},
            EP_G2{bfr, x, mask, rec_out, ximp_out, t});

        // G3: gi, M=512, N=3072, K=512
        gemm_k<128,128,8,8,8><<<dim3(3072/128, 512/128), 256>>>(
            2*FV, AL_G3{ximp_out, mask, t}, BL_G3{Wih}, EP_G3{bih});

        // GRU elementwise update
        gru_k<<<(BV*HV)/256, 256>>>(t, (t == TV-1) ? hfin : nullptr);
    }

    final_k<<<1, TV>>>(out);
}